// round 3
// baseline (speedup 1.0000x reference)
#include <cuda_runtime.h>

// B=128, N=1024. out[b,k] = a[b,j] - a[b,i] over strict upper triangle (j>i),
// row-major pair order. Row i starts at off(i) = i*(N-1) - i*(i-1)/2.

constexpr int N_ELEM  = 1024;
constexpr int M_PAIRS = N_ELEM * (N_ELEM - 1) / 2;   // 523776
constexpr int M4      = M_PAIRS / 4;                 // 130944
constexpr int THREADS = 256;
constexpr int IPT     = 4;
constexpr int K4_PER_BLOCK = THREADS * IPT;          // 1024
// shifted-copy pitch in floats: 1028*4 bytes = 4112 B, 16B-aligned
constexpr int PITCH   = N_ELEM + 4;

__device__ __forceinline__ int row_off(int i) {
    return i * (N_ELEM - 1) - ((i * (i - 1)) >> 1);
}

__global__ __launch_bounds__(THREADS)
void relpos_kernel(const float* __restrict__ in, float* __restrict__ out) {
    // 4 shifted copies: sh[r*PITCH + m] = a[m + r]  (m in [0, N-r))
    __shared__ float sh[4 * PITCH];

    const int b = blockIdx.y;
    const float* a = in + (size_t)b * N_ELEM;

    // Stage input + build shifted copies. Each thread loads one float4.
    {
        const float4 v = reinterpret_cast<const float4*>(a)[threadIdx.x];
        const int idx = threadIdx.x * 4;
        const float vv[4] = {v.x, v.y, v.z, v.w};
        #pragma unroll
        for (int e = 0; e < 4; e++) {
            const int x = idx + e;          // global element index
            const float val = vv[e];
            #pragma unroll
            for (int r = 0; r < 4; r++) {
                const int m = x - r;
                if (m >= 0) sh[r * PITCH + m] = val;
            }
        }
    }
    __syncthreads();

    float* outb = out + (size_t)b * M_PAIRS;
    const int base = blockIdx.x * K4_PER_BLOCK + threadIdx.x;

    #pragma unroll
    for (int it = 0; it < IPT; it++) {
        const int k4 = base + it * THREADS;
        if (k4 >= M4) continue;

        const int k = k4 << 2;

        // i = floor((2047 - sqrt(2047^2 - 8k)) / 2); disc < 2^24 exact in fp32.
        const int disc = 2047 * 2047 - (k << 3);
        int i = (int)(0.5f * (2047.0f - sqrtf((float)disc)));
        if (i < 0) i = 0;
        while (row_off(i + 1) <= k) ++i;
        while (row_off(i) > k) --i;

        int j = i + 1 + (k - row_off(i));
        float ai = sh[i];  // copy 0 == a[]

        float4 res;
        if (j + 3 < N_ELEM) {
            // All 4 elements in row i: one conflict-free LDS.128 from the
            // shifted copy whose alignment matches j.
            const int r = j & 3;
            const float4 v = *reinterpret_cast<const float4*>(&sh[r * PITCH + (j - r)]);
            res = make_float4(v.x - ai, v.y - ai, v.z - ai, v.w - ai);
        } else {
            // Row-crossing pack (~0.8% of packs): scalar path.
            float r0, r1, r2, r3;
            r0 = sh[j] - ai; if (++j == N_ELEM) { ++i; j = i + 1; ai = sh[i]; }
            r1 = sh[j] - ai; if (++j == N_ELEM) { ++i; j = i + 1; ai = sh[i]; }
            r2 = sh[j] - ai; if (++j == N_ELEM) { ++i; j = i + 1; ai = sh[i]; }
            r3 = sh[j] - ai;
            res = make_float4(r0, r1, r2, r3);
        }

        // Streaming store: output has no reuse, don't pollute L2.
        __stcs(reinterpret_cast<float4*>(outb) + k4, res);
    }
}

extern "C" void kernel_launch(void* const* d_in, const int* in_sizes, int n_in,
                              void* d_out, int out_size) {
    const float* in = (const float*)d_in[0];
    float* out = (float*)d_out;
    const int B = in_sizes[0] / N_ELEM;   // 128

    dim3 grid((M4 + K4_PER_BLOCK - 1) / K4_PER_BLOCK, B);  // (128, 128)
    relpos_kernel<<<grid, THREADS>>>(in, out);
}

// round 4
// speedup vs baseline: 1.1267x; 1.1267x over previous
#include <cuda_runtime.h>

// B=128, N=1024. out[b,k] = a[b,j] - a[b,i] over strict upper triangle (j>i),
// row-major pair order. Row i starts at off(i) = (i*(2047-i))/2.

constexpr int N_ELEM  = 1024;
constexpr int M_PAIRS = N_ELEM * (N_ELEM - 1) / 2;   // 523776
constexpr int M4      = M_PAIRS / 4;                 // 130944
constexpr int THREADS = 256;
constexpr int IPT     = 8;                           // float4s per thread
constexpr int K4_PER_BLOCK = THREADS * IPT;          // 2048
constexpr int PITCH   = N_ELEM + 4;                  // 16B-aligned copy pitch

__device__ __forceinline__ int row_off(int i) {
    // off(i) = i*(N-1) - i*(i-1)/2 = (i*(2047-i)) >> 1  (exact, even product)
    return (i * (2047 - i)) >> 1;
}

// Branch-free row index for flat pair-index q: largest i with off(i) <= q.
__device__ __forceinline__ int row_index(int q) {
    // i_real solves x(2047-x)/2 = q; disc = 2047^2 - 8q < 2^24 -> exact fp32.
    const float s = sqrtf((float)(2047 * 2047 - (q << 3)));
    int i = (int)(0.5f * (2047.0f - s));          // error <= 1e-4 -> i in {t-1,t,t+1}
    i += (row_off(i + 1) <= q);
    i -= (row_off(i) > q);                         // note: uses corrected-by-+1 value? no:
    return i;
}
// NOTE on row_index: the two corrections must both reference the ORIGINAL i0.
// Re-derivation below in the kernel uses the safe two-read form.

__global__ __launch_bounds__(THREADS)
void relpos_kernel(const float* __restrict__ in, float* __restrict__ out) {
    // 4 shifted copies: sh[r*PITCH + m] = a[m + r]
    __shared__ float sh[4 * PITCH];

    const int b = blockIdx.y;
    const float* a = in + (size_t)b * N_ELEM;

    // Stage input + build shifted copies (one float4 per thread).
    {
        const float4 v = reinterpret_cast<const float4*>(a)[threadIdx.x];
        const int idx = threadIdx.x * 4;
        const float vv[4] = {v.x, v.y, v.z, v.w};
        #pragma unroll
        for (int e = 0; e < 4; e++) {
            const int x = idx + e;
            const float val = vv[e];
            #pragma unroll
            for (int r = 0; r < 4; r++) {
                const int m = x - r;
                if (m >= 0) sh[r * PITCH + m] = val;
            }
        }
    }
    __syncthreads();

    float4* outb = reinterpret_cast<float4*>(out + (size_t)b * M_PAIRS);
    const int base = blockIdx.x * K4_PER_BLOCK + threadIdx.x;

    #pragma unroll
    for (int it = 0; it < IPT; it++) {
        const int k4 = base + it * THREADS;
        if (k4 >= M4) continue;                    // only last x-block partial

        const int k = k4 << 2;

        // Branch-free row index (corrections from the original estimate i0).
        const float s = sqrtf((float)(2047 * 2047 - (k << 3)));
        const int i0 = (int)(0.5f * (2047.0f - s));
        const int up = (row_off(i0 + 1) <= k);     // i0 == i-1 case
        const int dn = (row_off(i0) > k);          // i0 == i+1 case
        const int i  = i0 + up - dn;

        const int j = i + 1 + (k - row_off(i));
        float4 res;

        if (j + 3 < N_ELEM) {
            // Whole pack in row i: conflict-free LDS.128 from matching shifted copy.
            const float ai = sh[i];
            const int r = j & 3;
            const float4 v = *reinterpret_cast<const float4*>(&sh[r * PITCH + (j - r)]);
            res = make_float4(v.x - ai, v.y - ai, v.z - ai, v.w - ai);
        } else {
            // Row-crossing pack (~0.8%): per-element closed form, branch-free.
            float rr[4];
            #pragma unroll
            for (int e = 0; e < 4; e++) {
                const int q = k + e;
                const float se = sqrtf((float)(2047 * 2047 - (q << 3)));
                const int e0 = (int)(0.5f * (2047.0f - se));
                const int eu = (row_off(e0 + 1) <= q);
                const int ed = (row_off(e0) > q);
                const int ii = e0 + eu - ed;
                const int jj = ii + 1 + (q - row_off(ii));
                rr[e] = sh[jj] - sh[ii];
            }
            res = make_float4(rr[0], rr[1], rr[2], rr[3]);
        }

        outb[k4] = res;
    }
}

extern "C" void kernel_launch(void* const* d_in, const int* in_sizes, int n_in,
                              void* d_out, int out_size) {
    const float* in = (const float*)d_in[0];
    float* out = (float*)d_out;
    const int B = in_sizes[0] / N_ELEM;   // 128

    dim3 grid((M4 + K4_PER_BLOCK - 1) / K4_PER_BLOCK, B);  // (64, 128)
    relpos_kernel<<<grid, THREADS>>>(in, out);
}